// round 1
// baseline (speedup 1.0000x reference)
#include <cuda_runtime.h>
#include <math.h>

#define N_NODES 50000
#define DIM     128
#define HEADS   4
#define HD      512            // HEADS*DIM
#define N_EDGES 400000
#define ETOT    450000         // edges + self loops
#define LN_EPS  1e-5f
#define NEG_SLOPE 0.2f

// ---------------- scratch (device globals; no allocation allowed) ----------
__device__ float    g_xl[(size_t)N_NODES * HD];
__device__ float    g_xr[(size_t)N_NODES * HD];
__device__ float    g_agg[(size_t)N_NODES * HD];
__device__ float    g_e[(size_t)ETOT * HEADS];
__device__ unsigned g_emax[N_NODES * HEADS];
__device__ float    g_denom[N_NODES * HEADS];
__device__ float    g_y1[(size_t)N_NODES * DIM];
__device__ float    g_mid[(size_t)N_NODES * 2 * DIM];
__device__ float    g_z[(size_t)N_NODES * DIM];

// ---------------- helpers --------------------------------------------------
__device__ __forceinline__ float wsum(float v) {
#pragma unroll
    for (int o = 16; o; o >>= 1) v += __shfl_xor_sync(0xffffffffu, v, o);
    return v;
}
// monotone float<->uint encoding for atomicMax on signed floats
__device__ __forceinline__ unsigned f2o(float f) {
    unsigned u = __float_as_uint(f);
    return (u >> 31) ? ~u : (u | 0x80000000u);
}
__device__ __forceinline__ float o2f(unsigned u) {
    return (u >> 31) ? __uint_as_float(u & 0x7fffffffu) : __uint_as_float(~u);
}
__device__ __forceinline__ float gelu_exact(float v) {
    return 0.5f * v * (1.0f + erff(v * 0.70710678118654752f));
}
__device__ __forceinline__ float lrelu(float v) { return fmaxf(v, NEG_SLOPE * v); }

// ---------------- GEMM: C[M,Nn] = A[M,K] @ B[Nn,K]^T + bias (+epilogue) ----
// BM=BN=128 tile, KC=32 k-chunk, 256 threads, 8x8 micro-tile (split 4+4).
#define GKC   32
#define GBMN  128
#define GROWP 132   // 128 + 4 pad (keeps 16B alignment: 132*4 % 16 == 0)

template <int EPI>  // 0: bias  1: bias+gelu  2: bias+residual(R)
__global__ __launch_bounds__(256)
void gemm_nt(const float* __restrict__ A, const float* __restrict__ B,
             const float* __restrict__ bias, const float* __restrict__ R,
             float* __restrict__ C, int M, int Nn, int K)
{
    __shared__ float As[GKC * GROWP];
    __shared__ float Bs[GKC * GROWP];
    const int tid = threadIdx.x;
    const int tx = tid & 15, ty = tid >> 4;
    const int rb = blockIdx.x * GBMN, cb = blockIdx.y * GBMN;

    float acc[8][8];
#pragma unroll
    for (int i = 0; i < 8; i++)
#pragma unroll
        for (int j = 0; j < 8; j++) acc[i][j] = 0.0f;

    for (int kc = 0; kc < K; kc += GKC) {
        // load tiles (transposed into smem: [k][row])
#pragma unroll
        for (int it = 0; it < 4; it++) {
            int i = tid + it * 256;          // 0..1023
            int row = i >> 3;                // /8   (GKC/4 = 8 float4 per row)
            int k4  = i & 7;
            int gr  = rb + row;
            float4 v = make_float4(0.f, 0.f, 0.f, 0.f);
            if (gr < M) v = *(const float4*)&A[(size_t)gr * K + kc + k4 * 4];
            As[(k4 * 4 + 0) * GROWP + row] = v.x;
            As[(k4 * 4 + 1) * GROWP + row] = v.y;
            As[(k4 * 4 + 2) * GROWP + row] = v.z;
            As[(k4 * 4 + 3) * GROWP + row] = v.w;
            float4 w = *(const float4*)&B[(size_t)(cb + row) * K + kc + k4 * 4];
            Bs[(k4 * 4 + 0) * GROWP + row] = w.x;
            Bs[(k4 * 4 + 1) * GROWP + row] = w.y;
            Bs[(k4 * 4 + 2) * GROWP + row] = w.z;
            Bs[(k4 * 4 + 3) * GROWP + row] = w.w;
        }
        __syncthreads();
#pragma unroll
        for (int k = 0; k < GKC; k++) {
            float a[8], b[8];
            *(float4*)(a)     = *(const float4*)&As[k * GROWP + ty * 4];
            *(float4*)(a + 4) = *(const float4*)&As[k * GROWP + 64 + ty * 4];
            *(float4*)(b)     = *(const float4*)&Bs[k * GROWP + tx * 4];
            *(float4*)(b + 4) = *(const float4*)&Bs[k * GROWP + 64 + tx * 4];
#pragma unroll
            for (int i = 0; i < 8; i++)
#pragma unroll
                for (int j = 0; j < 8; j++) acc[i][j] += a[i] * b[j];
        }
        __syncthreads();
    }

    // epilogue: rows {ty*4+i, 64+ty*4+i}, cols {tx*4+j, 64+tx*4+j}
#pragma unroll
    for (int rg = 0; rg < 2; rg++) {
#pragma unroll
        for (int i = 0; i < 4; i++) {
            int row = rb + rg * 64 + ty * 4 + i;
            if (row >= M) continue;
#pragma unroll
            for (int cg = 0; cg < 2; cg++) {
                int col = cb + cg * 64 + tx * 4;
                const float* ap = &acc[rg * 4 + i][cg * 4];
                float4 bi = *(const float4*)&bias[col];
                float4 v;
                v.x = ap[0] + bi.x; v.y = ap[1] + bi.y;
                v.z = ap[2] + bi.z; v.w = ap[3] + bi.w;
                if (EPI == 1) {
                    v.x = gelu_exact(v.x); v.y = gelu_exact(v.y);
                    v.z = gelu_exact(v.z); v.w = gelu_exact(v.w);
                } else if (EPI == 2) {
                    float4 r = *(const float4*)&R[(size_t)row * Nn + col];
                    v.x += r.x; v.y += r.y; v.z += r.z; v.w += r.w;
                }
                *(float4*)&C[(size_t)row * Nn + col] = v;
            }
        }
    }
}

// ---------------- zero scratch (agg, denom, emax) ---------------------------
__global__ void zero_scratch()
{
    int idx = blockIdx.x * blockDim.x + threadIdx.x;   // 6.4M threads
    ((float4*)g_agg)[idx] = make_float4(0.f, 0.f, 0.f, 0.f);
    if (idx < N_NODES * HEADS) {
        g_denom[idx] = 0.0f;
        g_emax[idx]  = 0u;   // encodes "below any real value"
    }
}

// ---------------- edge pass A: attention logits + segment max ---------------
__global__ void edge_attn(const int* __restrict__ ei, const float* __restrict__ att)
{
    int wid  = (blockIdx.x * blockDim.x + threadIdx.x) >> 5;
    int lane = threadIdx.x & 31;
    if (wid >= ETOT) return;
    int src, dst;
    if (wid < N_EDGES) { src = ei[wid]; dst = ei[N_EDGES + wid]; }
    else               { src = dst = wid - N_EDGES; }

    const float4* xlp = (const float4*)(g_xl + (size_t)src * HD);
    const float4* xrp = (const float4*)(g_xr + (size_t)dst * HD);
    const float4* at4 = (const float4*)att;

    float e[HEADS];
#pragma unroll
    for (int h = 0; h < HEADS; h++) {
        float4 a = xlp[h * 32 + lane];
        float4 b = xrp[h * 32 + lane];
        float4 t = at4[h * 32 + lane];
        float s = lrelu(a.x + b.x) * t.x + lrelu(a.y + b.y) * t.y
                + lrelu(a.z + b.z) * t.z + lrelu(a.w + b.w) * t.w;
        e[h] = wsum(s);
    }
    if (lane == 0) {
        *(float4*)&g_e[(size_t)wid * 4] = make_float4(e[0], e[1], e[2], e[3]);
#pragma unroll
        for (int h = 0; h < HEADS; h++)
            atomicMax(&g_emax[dst * HEADS + h], f2o(e[h]));
    }
}

// ---------------- edge pass B: exp + segment sum ----------------------------
__global__ void edge_softmax(const int* __restrict__ ei)
{
    int id = blockIdx.x * blockDim.x + threadIdx.x;
    if (id >= ETOT) return;
    int dst = (id < N_EDGES) ? ei[N_EDGES + id] : (id - N_EDGES);
    float4 e4 = *(const float4*)&g_e[(size_t)id * 4];
    uint4  m4 = *(const uint4*)&g_emax[dst * HEADS];
    float4 ee;
    ee.x = expf(e4.x - o2f(m4.x));
    ee.y = expf(e4.y - o2f(m4.y));
    ee.z = expf(e4.z - o2f(m4.z));
    ee.w = expf(e4.w - o2f(m4.w));
    atomicAdd(&g_denom[dst * HEADS + 0], ee.x);
    atomicAdd(&g_denom[dst * HEADS + 1], ee.y);
    atomicAdd(&g_denom[dst * HEADS + 2], ee.z);
    atomicAdd(&g_denom[dst * HEADS + 3], ee.w);
    *(float4*)&g_e[(size_t)id * 4] = ee;
}

// ---------------- edge pass C: weighted aggregation -------------------------
__global__ void edge_aggregate(const int* __restrict__ ei)
{
    int wid  = (blockIdx.x * blockDim.x + threadIdx.x) >> 5;
    int lane = threadIdx.x & 31;
    if (wid >= ETOT) return;
    int src, dst;
    if (wid < N_EDGES) { src = ei[wid]; dst = ei[N_EDGES + wid]; }
    else               { src = dst = wid - N_EDGES; }

    float4 ee = __ldg((const float4*)&g_e[(size_t)wid * 4]);
    float4 dn = __ldg((const float4*)&g_denom[dst * HEADS]);
    float al[HEADS];
    al[0] = ee.x / (dn.x + 1e-16f);
    al[1] = ee.y / (dn.y + 1e-16f);
    al[2] = ee.z / (dn.z + 1e-16f);
    al[3] = ee.w / (dn.w + 1e-16f);

    const float4* xlp  = (const float4*)(g_xl + (size_t)src * HD);
    float4*       aggp = (float4*)(g_agg + (size_t)dst * HD);
#pragma unroll
    for (int h = 0; h < HEADS; h++) {
        float4 v = xlp[h * 32 + lane];
        float  a = al[h];
        atomicAdd(&aggp[h * 32 + lane],
                  make_float4(v.x * a, v.y * a, v.z * a, v.w * a));
    }
}

// ---------------- head-mean + bias + residual + LN1 -> y1 -------------------
__global__ void fuse_ln1(const float* __restrict__ x, const float* __restrict__ bias,
                         const float* __restrict__ g1, const float* __restrict__ be1)
{
    int row  = (blockIdx.x * blockDim.x + threadIdx.x) >> 5;
    int lane = threadIdx.x & 31;
    if (row >= N_NODES) return;
    const float4* ag = (const float4*)(g_agg + (size_t)row * HD);
    float4 s0 = ag[lane], s1 = ag[32 + lane], s2 = ag[64 + lane], s3 = ag[96 + lane];
    float4 xb = ((const float4*)x)[(size_t)row * 32 + lane];
    float4 b4 = ((const float4*)bias)[lane];
    float4 v;
    v.x = xb.x + 0.25f * (s0.x + s1.x + s2.x + s3.x) + b4.x;
    v.y = xb.y + 0.25f * (s0.y + s1.y + s2.y + s3.y) + b4.y;
    v.z = xb.z + 0.25f * (s0.z + s1.z + s2.z + s3.z) + b4.z;
    v.w = xb.w + 0.25f * (s0.w + s1.w + s2.w + s3.w) + b4.w;

    float mu = wsum(v.x + v.y + v.z + v.w) * (1.0f / DIM);
    float dx = v.x - mu, dy = v.y - mu, dz = v.z - mu, dw = v.w - mu;
    float var = wsum(dx * dx + dy * dy + dz * dz + dw * dw) * (1.0f / DIM);
    float rstd = rsqrtf(var + LN_EPS);
    float4 g = ((const float4*)g1)[lane];
    float4 b = ((const float4*)be1)[lane];
    float4 o;
    o.x = dx * rstd * g.x + b.x;  o.y = dy * rstd * g.y + b.y;
    o.z = dz * rstd * g.z + b.z;  o.w = dw * rstd * g.w + b.w;
    ((float4*)g_y1)[(size_t)row * 32 + lane] = o;
}

// ---------------- LN2 on z -> out -------------------------------------------
__global__ void ln2_kernel(const float* __restrict__ g2, const float* __restrict__ be2,
                           float* __restrict__ out)
{
    int row  = (blockIdx.x * blockDim.x + threadIdx.x) >> 5;
    int lane = threadIdx.x & 31;
    if (row >= N_NODES) return;
    float4 v = ((const float4*)g_z)[(size_t)row * 32 + lane];
    float mu = wsum(v.x + v.y + v.z + v.w) * (1.0f / DIM);
    float dx = v.x - mu, dy = v.y - mu, dz = v.z - mu, dw = v.w - mu;
    float var = wsum(dx * dx + dy * dy + dz * dz + dw * dw) * (1.0f / DIM);
    float rstd = rsqrtf(var + LN_EPS);
    float4 g = ((const float4*)g2)[lane];
    float4 b = ((const float4*)be2)[lane];
    float4 o;
    o.x = dx * rstd * g.x + b.x;  o.y = dy * rstd * g.y + b.y;
    o.z = dz * rstd * g.z + b.z;  o.w = dw * rstd * g.w + b.w;
    ((float4*)out)[(size_t)row * 32 + lane] = o;
}

// ---------------- launch -----------------------------------------------------
extern "C" void kernel_launch(void* const* d_in, const int* in_sizes, int n_in,
                              void* d_out, int out_size)
{
    const float* x    = (const float*)d_in[0];
    const int*   ei   = (const int*)d_in[1];
    const float* Wl   = (const float*)d_in[2];
    const float* bl   = (const float*)d_in[3];
    const float* Wr   = (const float*)d_in[4];
    const float* br   = (const float*)d_in[5];
    const float* att  = (const float*)d_in[6];
    const float* bias = (const float*)d_in[7];
    const float* g1   = (const float*)d_in[8];
    const float* be1  = (const float*)d_in[9];
    const float* W1   = (const float*)d_in[10];
    const float* b1   = (const float*)d_in[11];
    const float* W2   = (const float*)d_in[12];
    const float* b2   = (const float*)d_in[13];
    const float* g2   = (const float*)d_in[14];
    const float* be2  = (const float*)d_in[15];
    float* out = (float*)d_out;

    float *p_xl, *p_xr, *p_y1, *p_mid, *p_z;
    cudaGetSymbolAddress((void**)&p_xl,  g_xl);
    cudaGetSymbolAddress((void**)&p_xr,  g_xr);
    cudaGetSymbolAddress((void**)&p_y1,  g_y1);
    cudaGetSymbolAddress((void**)&p_mid, g_mid);
    cudaGetSymbolAddress((void**)&p_z,   g_z);

    const int MB = (N_NODES + GBMN - 1) / GBMN;   // 391

    gemm_nt<0><<<dim3(MB, HD / GBMN), 256>>>(x, Wl, bl, nullptr, p_xl, N_NODES, HD, DIM);
    gemm_nt<0><<<dim3(MB, HD / GBMN), 256>>>(x, Wr, br, nullptr, p_xr, N_NODES, HD, DIM);
    zero_scratch<<<(N_NODES * HD / 4) / 256, 256>>>();
    edge_attn<<<(ETOT * 32 + 255) / 256, 256>>>(ei, att);
    edge_softmax<<<(ETOT + 255) / 256, 256>>>(ei);
    edge_aggregate<<<(ETOT * 32 + 255) / 256, 256>>>(ei);
    fuse_ln1<<<(N_NODES * 32) / 256, 256>>>(x, bias, g1, be1);
    gemm_nt<1><<<dim3(MB, (2 * DIM) / GBMN), 256>>>(p_y1, W1, b1, nullptr, p_mid,
                                                    N_NODES, 2 * DIM, DIM);
    gemm_nt<2><<<dim3(MB, DIM / GBMN), 256>>>(p_mid, W2, b2, p_y1, p_z,
                                              N_NODES, DIM, 2 * DIM);
    ln2_kernel<<<(N_NODES * 32) / 256, 256>>>(g2, be2, out);
}

// round 2
// speedup vs baseline: 1.3530x; 1.3530x over previous
#include <cuda_runtime.h>
#include <cuda_bf16.h>
#include <math.h>

#define N_NODES 50000
#define DIM     128
#define HEADS   4
#define HD      512            // HEADS*DIM
#define N_EDGES 400000
#define ETOT    450000         // edges + self loops
#define LN_EPS  1e-5f
#define NEG_SLOPE 0.2f

// ---------------- scratch (device globals; no allocation allowed) ----------
__device__ float    g_xl[(size_t)N_NODES * HD];
__device__ float    g_xr[(size_t)N_NODES * HD];
__device__ float    g_agg[(size_t)N_NODES * HD];
__device__ float    g_e[(size_t)ETOT * HEADS];
__device__ unsigned g_emax[N_NODES * HEADS];
__device__ float    g_denom[N_NODES * HEADS];
__device__ float    g_y1[(size_t)N_NODES * DIM];
__device__ float    g_mid[(size_t)N_NODES * 2 * DIM];
__device__ float    g_z[(size_t)N_NODES * DIM];

// ---------------- helpers --------------------------------------------------
__device__ __forceinline__ float wsum(float v) {
#pragma unroll
    for (int o = 16; o; o >>= 1) v += __shfl_xor_sync(0xffffffffu, v, o);
    return v;
}
__device__ __forceinline__ unsigned f2o(float f) {
    unsigned u = __float_as_uint(f);
    return (u >> 31) ? ~u : (u | 0x80000000u);
}
__device__ __forceinline__ float o2f(unsigned u) {
    return (u >> 31) ? __uint_as_float(u & 0x7fffffffu) : __uint_as_float(~u);
}
__device__ __forceinline__ float gelu_exact(float v) {
    return 0.5f * v * (1.0f + erff(v * 0.70710678118654752f));
}
__device__ __forceinline__ float lrelu(float v) { return fmaxf(v, NEG_SLOPE * v); }

// ---------------- tensor-core GEMM: C[M,Nn] = A[M,K] @ B[Nn,K]^T + epi -----
// bf16 hi/lo split (3 MMA passes: ah*bh + ah*bl + al*bh) for fp32-like accuracy.
// Block tile 128x128, 256 threads (8 warps), warp tile 32x64, K-chunk 32.
#define PITCH 40   // bf16 elems per smem row (32 + 8 pad) -> ldmatrix conflict-free

__device__ __forceinline__ void ldsm4(unsigned &r0, unsigned &r1, unsigned &r2,
                                      unsigned &r3, unsigned addr) {
    asm volatile("ldmatrix.sync.aligned.m8n8.x4.shared.b16 {%0,%1,%2,%3},[%4];"
                 : "=r"(r0), "=r"(r1), "=r"(r2), "=r"(r3) : "r"(addr));
}
__device__ __forceinline__ void mma16816(float* d, const unsigned* a, const unsigned* b) {
    asm volatile(
        "mma.sync.aligned.m16n8k16.row.col.f32.bf16.bf16.f32 "
        "{%0,%1,%2,%3},{%4,%5,%6,%7},{%8,%9},{%0,%1,%2,%3};"
        : "+f"(d[0]), "+f"(d[1]), "+f"(d[2]), "+f"(d[3])
        : "r"(a[0]), "r"(a[1]), "r"(a[2]), "r"(a[3]), "r"(b[0]), "r"(b[1]));
}

template <int EPI>  // 0: bias  1: bias+gelu  2: bias+residual(R)
__global__ __launch_bounds__(256, 2)
void gemm_mma(const float* __restrict__ A, const float* __restrict__ B,
              const float* __restrict__ bias, const float* __restrict__ R,
              float* __restrict__ C, int M, int Nn, int K)
{
    __shared__ __nv_bfloat16 sAh[128 * PITCH];
    __shared__ __nv_bfloat16 sAl[128 * PITCH];
    __shared__ __nv_bfloat16 sBh[128 * PITCH];
    __shared__ __nv_bfloat16 sBl[128 * PITCH];

    const int tid  = threadIdx.x;
    const int lane = tid & 31;
    const int warp = tid >> 5;
    const int wm = warp >> 1;          // 0..3 -> m offset wm*32
    const int wn = warp & 1;           // 0..1 -> n offset wn*64
    const int rb = blockIdx.x * 128, cb = blockIdx.y * 128;

    // ldmatrix lane->address components
    const int a_row = lane & 15;               // row within m16
    const int a_k   = (lane >> 4) << 3;        // 0 or 8
    const int b_n   = (lane & 7) + ((lane >> 4) << 3);  // 0..15 within n16
    const int b_k   = lane & 8;                // 0 or 8

    const unsigned baseAh = (unsigned)__cvta_generic_to_shared(sAh);
    const unsigned baseAl = (unsigned)__cvta_generic_to_shared(sAl);
    const unsigned baseBh = (unsigned)__cvta_generic_to_shared(sBh);
    const unsigned baseBl = (unsigned)__cvta_generic_to_shared(sBl);

    float acc[2][8][4];
#pragma unroll
    for (int i = 0; i < 2; i++)
#pragma unroll
        for (int j = 0; j < 8; j++)
#pragma unroll
            for (int q = 0; q < 4; q++) acc[i][j][q] = 0.0f;

    for (int kc = 0; kc < K; kc += 32) {
        // ---- global -> smem with bf16 hi/lo split ----
#pragma unroll
        for (int it = 0; it < 4; it++) {
            int i   = tid + it * 256;    // 0..1023
            int row = i >> 3;            // 0..127
            int kq  = (i & 7) << 2;      // 0,4,...,28
            // A tile (row guarded)
            float4 av = make_float4(0.f, 0.f, 0.f, 0.f);
            if (rb + row < M) av = *(const float4*)&A[(size_t)(rb + row) * K + kc + kq];
            __nv_bfloat16 h0 = __float2bfloat16(av.x), h1 = __float2bfloat16(av.y);
            __nv_bfloat16 h2 = __float2bfloat16(av.z), h3 = __float2bfloat16(av.w);
            __nv_bfloat16 l0 = __float2bfloat16(av.x - __bfloat162float(h0));
            __nv_bfloat16 l1 = __float2bfloat16(av.y - __bfloat162float(h1));
            __nv_bfloat16 l2 = __float2bfloat16(av.z - __bfloat162float(h2));
            __nv_bfloat16 l3 = __float2bfloat16(av.w - __bfloat162float(h3));
            int off = row * PITCH + kq;
            *(__nv_bfloat162*)&sAh[off]     = __halves2bfloat162(h0, h1);
            *(__nv_bfloat162*)&sAh[off + 2] = __halves2bfloat162(h2, h3);
            *(__nv_bfloat162*)&sAl[off]     = __halves2bfloat162(l0, l1);
            *(__nv_bfloat162*)&sAl[off + 2] = __halves2bfloat162(l2, l3);
            // B tile (Nn always multiple of 128 -> unguarded)
            float4 bv = *(const float4*)&B[(size_t)(cb + row) * K + kc + kq];
            __nv_bfloat16 p0 = __float2bfloat16(bv.x), p1 = __float2bfloat16(bv.y);
            __nv_bfloat16 p2 = __float2bfloat16(bv.z), p3 = __float2bfloat16(bv.w);
            __nv_bfloat16 q0 = __float2bfloat16(bv.x - __bfloat162float(p0));
            __nv_bfloat16 q1 = __float2bfloat16(bv.y - __bfloat162float(p1));
            __nv_bfloat16 q2 = __float2bfloat16(bv.z - __bfloat162float(p2));
            __nv_bfloat16 q3 = __float2bfloat16(bv.w - __bfloat162float(p3));
            *(__nv_bfloat162*)&sBh[off]     = __halves2bfloat162(p0, p1);
            *(__nv_bfloat162*)&sBh[off + 2] = __halves2bfloat162(p2, p3);
            *(__nv_bfloat162*)&sBl[off]     = __halves2bfloat162(q0, q1);
            *(__nv_bfloat162*)&sBl[off + 2] = __halves2bfloat162(q2, q3);
        }
        __syncthreads();

        // ---- compute: 2 k16 steps ----
#pragma unroll
        for (int s = 0; s < 2; s++) {
            unsigned ah[2][4], al[2][4];
#pragma unroll
            for (int mt = 0; mt < 2; mt++) {
                unsigned offA = (unsigned)(((wm * 32 + mt * 16 + a_row) * PITCH
                                            + s * 16 + a_k) * 2);
                ldsm4(ah[mt][0], ah[mt][1], ah[mt][2], ah[mt][3], baseAh + offA);
                ldsm4(al[mt][0], al[mt][1], al[mt][2], al[mt][3], baseAl + offA);
            }
#pragma unroll
            for (int nt = 0; nt < 4; nt++) {
                unsigned offB = (unsigned)(((wn * 64 + nt * 16 + b_n) * PITCH
                                            + s * 16 + b_k) * 2);
                unsigned bh[4], bl[4];
                ldsm4(bh[0], bh[1], bh[2], bh[3], baseBh + offB);
                ldsm4(bl[0], bl[1], bl[2], bl[3], baseBl + offB);
#pragma unroll
                for (int mt = 0; mt < 2; mt++) {
                    mma16816(acc[mt][nt * 2 + 0], ah[mt], &bh[0]);
                    mma16816(acc[mt][nt * 2 + 0], ah[mt], &bl[0]);
                    mma16816(acc[mt][nt * 2 + 0], al[mt], &bh[0]);
                    mma16816(acc[mt][nt * 2 + 1], ah[mt], &bh[2]);
                    mma16816(acc[mt][nt * 2 + 1], ah[mt], &bl[2]);
                    mma16816(acc[mt][nt * 2 + 1], al[mt], &bh[2]);
                }
            }
        }
        __syncthreads();
    }

    // ---- epilogue ----
#pragma unroll
    for (int mt = 0; mt < 2; mt++) {
#pragma unroll
        for (int jj = 0; jj < 8; jj++) {
            int row0 = rb + wm * 32 + mt * 16 + (lane >> 2);
            int col  = cb + wn * 64 + jj * 8 + ((lane & 3) << 1);
            float2 bi = *(const float2*)&bias[col];
#pragma unroll
            for (int half = 0; half < 2; half++) {
                int row = row0 + half * 8;
                if (row >= M) continue;
                float v0 = acc[mt][jj][half * 2 + 0] + bi.x;
                float v1 = acc[mt][jj][half * 2 + 1] + bi.y;
                if (EPI == 1) { v0 = gelu_exact(v0); v1 = gelu_exact(v1); }
                else if (EPI == 2) {
                    float2 r = *(const float2*)&R[(size_t)row * Nn + col];
                    v0 += r.x; v1 += r.y;
                }
                *(float2*)&C[(size_t)row * Nn + col] = make_float2(v0, v1);
            }
        }
    }
}

// ---------------- zero scratch (agg, denom, emax) ---------------------------
__global__ void zero_scratch()
{
    int idx = blockIdx.x * blockDim.x + threadIdx.x;   // 6.4M threads
    ((float4*)g_agg)[idx] = make_float4(0.f, 0.f, 0.f, 0.f);
    if (idx < N_NODES * HEADS) {
        g_denom[idx] = 0.0f;
        g_emax[idx]  = 0u;
    }
}

// ---------------- edge pass A: attention logits + segment max ---------------
__global__ void edge_attn(const int* __restrict__ ei, const float* __restrict__ att)
{
    int wid  = (blockIdx.x * blockDim.x + threadIdx.x) >> 5;
    int lane = threadIdx.x & 31;
    if (wid >= ETOT) return;
    int src, dst;
    if (wid < N_EDGES) { src = ei[wid]; dst = ei[N_EDGES + wid]; }
    else               { src = dst = wid - N_EDGES; }

    const float4* xlp = (const float4*)(g_xl + (size_t)src * HD);
    const float4* xrp = (const float4*)(g_xr + (size_t)dst * HD);
    const float4* at4 = (const float4*)att;

    float e[HEADS];
#pragma unroll
    for (int h = 0; h < HEADS; h++) {
        float4 a = xlp[h * 32 + lane];
        float4 b = xrp[h * 32 + lane];
        float4 t = at4[h * 32 + lane];
        float s = lrelu(a.x + b.x) * t.x + lrelu(a.y + b.y) * t.y
                + lrelu(a.z + b.z) * t.z + lrelu(a.w + b.w) * t.w;
        e[h] = wsum(s);
    }
    if (lane == 0) {
        *(float4*)&g_e[(size_t)wid * 4] = make_float4(e[0], e[1], e[2], e[3]);
#pragma unroll
        for (int h = 0; h < HEADS; h++)
            atomicMax(&g_emax[dst * HEADS + h], f2o(e[h]));
    }
}

// ---------------- edge pass B: exp + segment sum ----------------------------
__global__ void edge_softmax(const int* __restrict__ ei)
{
    int id = blockIdx.x * blockDim.x + threadIdx.x;
    if (id >= ETOT) return;
    int dst = (id < N_EDGES) ? ei[N_EDGES + id] : (id - N_EDGES);
    float4 e4 = *(const float4*)&g_e[(size_t)id * 4];
    uint4  m4 = *(const uint4*)&g_emax[dst * HEADS];
    float4 ee;
    ee.x = expf(e4.x - o2f(m4.x));
    ee.y = expf(e4.y - o2f(m4.y));
    ee.z = expf(e4.z - o2f(m4.z));
    ee.w = expf(e4.w - o2f(m4.w));
    atomicAdd(&g_denom[dst * HEADS + 0], ee.x);
    atomicAdd(&g_denom[dst * HEADS + 1], ee.y);
    atomicAdd(&g_denom[dst * HEADS + 2], ee.z);
    atomicAdd(&g_denom[dst * HEADS + 3], ee.w);
    *(float4*)&g_e[(size_t)id * 4] = ee;
}

// ---------------- edge pass C: weighted aggregation -------------------------
__global__ void edge_aggregate(const int* __restrict__ ei)
{
    int wid  = (blockIdx.x * blockDim.x + threadIdx.x) >> 5;
    int lane = threadIdx.x & 31;
    if (wid >= ETOT) return;
    int src, dst;
    if (wid < N_EDGES) { src = ei[wid]; dst = ei[N_EDGES + wid]; }
    else               { src = dst = wid - N_EDGES; }

    float4 ee = __ldg((const float4*)&g_e[(size_t)wid * 4]);
    float4 dn = __ldg((const float4*)&g_denom[dst * HEADS]);
    float al[HEADS];
    al[0] = ee.x / (dn.x + 1e-16f);
    al[1] = ee.y / (dn.y + 1e-16f);
    al[2] = ee.z / (dn.z + 1e-16f);
    al[3] = ee.w / (dn.w + 1e-16f);

    const float4* xlp  = (const float4*)(g_xl + (size_t)src * HD);
    float4*       aggp = (float4*)(g_agg + (size_t)dst * HD);
#pragma unroll
    for (int h = 0; h < HEADS; h++) {
        float4 v = xlp[h * 32 + lane];
        float  a = al[h];
        atomicAdd(&aggp[h * 32 + lane],
                  make_float4(v.x * a, v.y * a, v.z * a, v.w * a));
    }
}

// ---------------- head-mean + bias + residual + LN1 -> y1 -------------------
__global__ void fuse_ln1(const float* __restrict__ x, const float* __restrict__ bias,
                         const float* __restrict__ g1, const float* __restrict__ be1)
{
    int row  = (blockIdx.x * blockDim.x + threadIdx.x) >> 5;
    int lane = threadIdx.x & 31;
    if (row >= N_NODES) return;
    const float4* ag = (const float4*)(g_agg + (size_t)row * HD);
    float4 s0 = ag[lane], s1 = ag[32 + lane], s2 = ag[64 + lane], s3 = ag[96 + lane];
    float4 xb = ((const float4*)x)[(size_t)row * 32 + lane];
    float4 b4 = ((const float4*)bias)[lane];
    float4 v;
    v.x = xb.x + 0.25f * (s0.x + s1.x + s2.x + s3.x) + b4.x;
    v.y = xb.y + 0.25f * (s0.y + s1.y + s2.y + s3.y) + b4.y;
    v.z = xb.z + 0.25f * (s0.z + s1.z + s2.z + s3.z) + b4.z;
    v.w = xb.w + 0.25f * (s0.w + s1.w + s2.w + s3.w) + b4.w;

    float mu = wsum(v.x + v.y + v.z + v.w) * (1.0f / DIM);
    float dx = v.x - mu, dy = v.y - mu, dz = v.z - mu, dw = v.w - mu;
    float var = wsum(dx * dx + dy * dy + dz * dz + dw * dw) * (1.0f / DIM);
    float rstd = rsqrtf(var + LN_EPS);
    float4 g = ((const float4*)g1)[lane];
    float4 b = ((const float4*)be1)[lane];
    float4 o;
    o.x = dx * rstd * g.x + b.x;  o.y = dy * rstd * g.y + b.y;
    o.z = dz * rstd * g.z + b.z;  o.w = dw * rstd * g.w + b.w;
    ((float4*)g_y1)[(size_t)row * 32 + lane] = o;
}

// ---------------- LN2 on z -> out -------------------------------------------
__global__ void ln2_kernel(const float* __restrict__ g2, const float* __restrict__ be2,
                           float* __restrict__ out)
{
    int row  = (blockIdx.x * blockDim.x + threadIdx.x) >> 5;
    int lane = threadIdx.x & 31;
    if (row >= N_NODES) return;
    float4 v = ((const float4*)g_z)[(size_t)row * 32 + lane];
    float mu = wsum(v.x + v.y + v.z + v.w) * (1.0f / DIM);
    float dx = v.x - mu, dy = v.y - mu, dz = v.z - mu, dw = v.w - mu;
    float var = wsum(dx * dx + dy * dy + dz * dz + dw * dw) * (1.0f / DIM);
    float rstd = rsqrtf(var + LN_EPS);
    float4 g = ((const float4*)g2)[lane];
    float4 b = ((const float4*)be2)[lane];
    float4 o;
    o.x = dx * rstd * g.x + b.x;  o.y = dy * rstd * g.y + b.y;
    o.z = dz * rstd * g.z + b.z;  o.w = dw * rstd * g.w + b.w;
    ((float4*)out)[(size_t)row * 32 + lane] = o;
}

// ---------------- launch -----------------------------------------------------
extern "C" void kernel_launch(void* const* d_in, const int* in_sizes, int n_in,
                              void* d_out, int out_size)
{
    const float* x    = (const float*)d_in[0];
    const int*   ei   = (const int*)d_in[1];
    const float* Wl   = (const float*)d_in[2];
    const float* bl   = (const float*)d_in[3];
    const float* Wr   = (const float*)d_in[4];
    const float* br   = (const float*)d_in[5];
    const float* att  = (const float*)d_in[6];
    const float* bias = (const float*)d_in[7];
    const float* g1   = (const float*)d_in[8];
    const float* be1  = (const float*)d_in[9];
    const float* W1   = (const float*)d_in[10];
    const float* b1   = (const float*)d_in[11];
    const float* W2   = (const float*)d_in[12];
    const float* b2   = (const float*)d_in[13];
    const float* g2   = (const float*)d_in[14];
    const float* be2  = (const float*)d_in[15];
    float* out = (float*)d_out;

    float *p_xl, *p_xr, *p_y1, *p_mid, *p_z;
    cudaGetSymbolAddress((void**)&p_xl,  g_xl);
    cudaGetSymbolAddress((void**)&p_xr,  g_xr);
    cudaGetSymbolAddress((void**)&p_y1,  g_y1);
    cudaGetSymbolAddress((void**)&p_mid, g_mid);
    cudaGetSymbolAddress((void**)&p_z,   g_z);

    const int MB = (N_NODES + 127) / 128;   // 391

    gemm_mma<0><<<dim3(MB, HD / 128), 256>>>(x, Wl, bl, nullptr, p_xl, N_NODES, HD, DIM);
    gemm_mma<0><<<dim3(MB, HD / 128), 256>>>(x, Wr, br, nullptr, p_xr, N_NODES, HD, DIM);
    zero_scratch<<<(N_NODES * HD / 4) / 256, 256>>>();
    edge_attn<<<(ETOT * 32 + 255) / 256, 256>>>(ei, att);
    edge_softmax<<<(ETOT + 255) / 256, 256>>>(ei);
    edge_aggregate<<<(ETOT * 32 + 255) / 256, 256>>>(ei);
    fuse_ln1<<<(N_NODES * 32) / 256, 256>>>(x, bias, g1, be1);
    gemm_mma<1><<<dim3(MB, (2 * DIM) / 128), 256>>>(p_y1, W1, b1, nullptr, p_mid,
                                                    N_NODES, 2 * DIM, DIM);
    gemm_mma<2><<<dim3(MB, DIM / 128), 256>>>(p_mid, W2, b2, p_y1, p_z,
                                              N_NODES, DIM, 2 * DIM);
    ln2_kernel<<<(N_NODES * 32) / 256, 256>>>(g2, be2, out);
}

// round 3
// speedup vs baseline: 1.9787x; 1.4625x over previous
#include <cuda_runtime.h>
#include <cuda_bf16.h>
#include <math.h>

#define N_NODES 50000
#define DIM     128
#define HEADS   4
#define HD      512            // HEADS*DIM
#define N_EDGES 400000
#define ETOT    450000         // edges + self loops
#define LN_EPS  1e-5f
#define NEG_SLOPE 0.2f

// ---------------- scratch (device globals; no allocation allowed) ----------
__device__ float g_xl[(size_t)N_NODES * HD];
__device__ float g_xr[(size_t)N_NODES * HD];
__device__ float g_y1[(size_t)N_NODES * DIM];
__device__ float g_mid[(size_t)N_NODES * 2 * DIM];
__device__ float g_z[(size_t)N_NODES * DIM];
// CSR scratch
__device__ int g_off[N_NODES + 1];
__device__ int g_cur[N_NODES];
__device__ int g_csr[ETOT];
__device__ int g_bsum[64];

// ---------------- helpers --------------------------------------------------
__device__ __forceinline__ float wsum(float v) {
#pragma unroll
    for (int o = 16; o; o >>= 1) v += __shfl_xor_sync(0xffffffffu, v, o);
    return v;
}
__device__ __forceinline__ float gelu_exact(float v) {
    return 0.5f * v * (1.0f + erff(v * 0.70710678118654752f));
}
__device__ __forceinline__ float lrelu(float v) { return fmaxf(v, NEG_SLOPE * v); }

// ---------------- tensor-core GEMM (unchanged from R2) ---------------------
#define PITCH 40

__device__ __forceinline__ void ldsm4(unsigned &r0, unsigned &r1, unsigned &r2,
                                      unsigned &r3, unsigned addr) {
    asm volatile("ldmatrix.sync.aligned.m8n8.x4.shared.b16 {%0,%1,%2,%3},[%4];"
                 : "=r"(r0), "=r"(r1), "=r"(r2), "=r"(r3) : "r"(addr));
}
__device__ __forceinline__ void mma16816(float* d, const unsigned* a, const unsigned* b) {
    asm volatile(
        "mma.sync.aligned.m16n8k16.row.col.f32.bf16.bf16.f32 "
        "{%0,%1,%2,%3},{%4,%5,%6,%7},{%8,%9},{%0,%1,%2,%3};"
        : "+f"(d[0]), "+f"(d[1]), "+f"(d[2]), "+f"(d[3])
        : "r"(a[0]), "r"(a[1]), "r"(a[2]), "r"(a[3]), "r"(b[0]), "r"(b[1]));
}

template <int EPI>  // 0: bias  1: bias+gelu  2: bias+residual(R)
__global__ __launch_bounds__(256, 2)
void gemm_mma(const float* __restrict__ A, const float* __restrict__ B,
              const float* __restrict__ bias, const float* __restrict__ R,
              float* __restrict__ C, int M, int Nn, int K)
{
    __shared__ __nv_bfloat16 sAh[128 * PITCH];
    __shared__ __nv_bfloat16 sAl[128 * PITCH];
    __shared__ __nv_bfloat16 sBh[128 * PITCH];
    __shared__ __nv_bfloat16 sBl[128 * PITCH];

    const int tid  = threadIdx.x;
    const int lane = tid & 31;
    const int warp = tid >> 5;
    const int wm = warp >> 1;
    const int wn = warp & 1;
    const int rb = blockIdx.x * 128, cb = blockIdx.y * 128;

    const int a_row = lane & 15;
    const int a_k   = (lane >> 4) << 3;
    const int b_n   = (lane & 7) + ((lane >> 4) << 3);
    const int b_k   = lane & 8;

    const unsigned baseAh = (unsigned)__cvta_generic_to_shared(sAh);
    const unsigned baseAl = (unsigned)__cvta_generic_to_shared(sAl);
    const unsigned baseBh = (unsigned)__cvta_generic_to_shared(sBh);
    const unsigned baseBl = (unsigned)__cvta_generic_to_shared(sBl);

    float acc[2][8][4];
#pragma unroll
    for (int i = 0; i < 2; i++)
#pragma unroll
        for (int j = 0; j < 8; j++)
#pragma unroll
            for (int q = 0; q < 4; q++) acc[i][j][q] = 0.0f;

    for (int kc = 0; kc < K; kc += 32) {
#pragma unroll
        for (int it = 0; it < 4; it++) {
            int i   = tid + it * 256;
            int row = i >> 3;
            int kq  = (i & 7) << 2;
            float4 av = make_float4(0.f, 0.f, 0.f, 0.f);
            if (rb + row < M) av = *(const float4*)&A[(size_t)(rb + row) * K + kc + kq];
            __nv_bfloat16 h0 = __float2bfloat16(av.x), h1 = __float2bfloat16(av.y);
            __nv_bfloat16 h2 = __float2bfloat16(av.z), h3 = __float2bfloat16(av.w);
            __nv_bfloat16 l0 = __float2bfloat16(av.x - __bfloat162float(h0));
            __nv_bfloat16 l1 = __float2bfloat16(av.y - __bfloat162float(h1));
            __nv_bfloat16 l2 = __float2bfloat16(av.z - __bfloat162float(h2));
            __nv_bfloat16 l3 = __float2bfloat16(av.w - __bfloat162float(h3));
            int off = row * PITCH + kq;
            *(__nv_bfloat162*)&sAh[off]     = __halves2bfloat162(h0, h1);
            *(__nv_bfloat162*)&sAh[off + 2] = __halves2bfloat162(h2, h3);
            *(__nv_bfloat162*)&sAl[off]     = __halves2bfloat162(l0, l1);
            *(__nv_bfloat162*)&sAl[off + 2] = __halves2bfloat162(l2, l3);
            float4 bv = *(const float4*)&B[(size_t)(cb + row) * K + kc + kq];
            __nv_bfloat16 p0 = __float2bfloat16(bv.x), p1 = __float2bfloat16(bv.y);
            __nv_bfloat16 p2 = __float2bfloat16(bv.z), p3 = __float2bfloat16(bv.w);
            __nv_bfloat16 q0 = __float2bfloat16(bv.x - __bfloat162float(p0));
            __nv_bfloat16 q1 = __float2bfloat16(bv.y - __bfloat162float(p1));
            __nv_bfloat16 q2 = __float2bfloat16(bv.z - __bfloat162float(p2));
            __nv_bfloat16 q3 = __float2bfloat16(bv.w - __bfloat162float(p3));
            *(__nv_bfloat162*)&sBh[off]     = __halves2bfloat162(p0, p1);
            *(__nv_bfloat162*)&sBh[off + 2] = __halves2bfloat162(p2, p3);
            *(__nv_bfloat162*)&sBl[off]     = __halves2bfloat162(q0, q1);
            *(__nv_bfloat162*)&sBl[off + 2] = __halves2bfloat162(q2, q3);
        }
        __syncthreads();

#pragma unroll
        for (int s = 0; s < 2; s++) {
            unsigned ah[2][4], al[2][4];
#pragma unroll
            for (int mt = 0; mt < 2; mt++) {
                unsigned offA = (unsigned)(((wm * 32 + mt * 16 + a_row) * PITCH
                                            + s * 16 + a_k) * 2);
                ldsm4(ah[mt][0], ah[mt][1], ah[mt][2], ah[mt][3], baseAh + offA);
                ldsm4(al[mt][0], al[mt][1], al[mt][2], al[mt][3], baseAl + offA);
            }
#pragma unroll
            for (int nt = 0; nt < 4; nt++) {
                unsigned offB = (unsigned)(((wn * 64 + nt * 16 + b_n) * PITCH
                                            + s * 16 + b_k) * 2);
                unsigned bh[4], bl[4];
                ldsm4(bh[0], bh[1], bh[2], bh[3], baseBh + offB);
                ldsm4(bl[0], bl[1], bl[2], bl[3], baseBl + offB);
#pragma unroll
                for (int mt = 0; mt < 2; mt++) {
                    mma16816(acc[mt][nt * 2 + 0], ah[mt], &bh[0]);
                    mma16816(acc[mt][nt * 2 + 0], ah[mt], &bl[0]);
                    mma16816(acc[mt][nt * 2 + 0], al[mt], &bh[0]);
                    mma16816(acc[mt][nt * 2 + 1], ah[mt], &bh[2]);
                    mma16816(acc[mt][nt * 2 + 1], ah[mt], &bl[2]);
                    mma16816(acc[mt][nt * 2 + 1], al[mt], &bh[2]);
                }
            }
        }
        __syncthreads();
    }

#pragma unroll
    for (int mt = 0; mt < 2; mt++) {
#pragma unroll
        for (int jj = 0; jj < 8; jj++) {
            int row0 = rb + wm * 32 + mt * 16 + (lane >> 2);
            int col  = cb + wn * 64 + jj * 8 + ((lane & 3) << 1);
            float2 bi = *(const float2*)&bias[col];
#pragma unroll
            for (int half = 0; half < 2; half++) {
                int row = row0 + half * 8;
                if (row >= M) continue;
                float v0 = acc[mt][jj][half * 2 + 0] + bi.x;
                float v1 = acc[mt][jj][half * 2 + 1] + bi.y;
                if (EPI == 1) { v0 = gelu_exact(v0); v1 = gelu_exact(v1); }
                else if (EPI == 2) {
                    float2 r = *(const float2*)&R[(size_t)row * Nn + col];
                    v0 += r.x; v1 += r.y;
                }
                *(float2*)&C[(size_t)row * Nn + col] = make_float2(v0, v1);
            }
        }
    }
}

// ================= CSR build ================================================
// deg stored temporarily in g_cur; offsets into g_off; adjacency in g_csr.
__global__ void csr_init()
{
    int i = blockIdx.x * blockDim.x + threadIdx.x;
    if (i < N_NODES) g_cur[i] = 1;   // self loop pre-counted
}
__global__ void csr_hist(const int* __restrict__ ei)
{
    int e = blockIdx.x * blockDim.x + threadIdx.x;
    if (e < N_EDGES) atomicAdd(&g_cur[ei[N_EDGES + e]], 1);
}
// block-level exclusive scan (1024/block), per-block totals -> g_bsum
__global__ __launch_bounds__(1024)
void csr_scan1()
{
    int tid = threadIdx.x, lane = tid & 31, warp = tid >> 5;
    int idx = blockIdx.x * 1024 + tid;
    int val = (idx < N_NODES) ? g_cur[idx] : 0;
    int v = val;
#pragma unroll
    for (int o = 1; o < 32; o <<= 1) {
        int t = __shfl_up_sync(0xffffffffu, v, o);
        if (lane >= o) v += t;
    }
    __shared__ int ws[32];
    if (lane == 31) ws[warp] = v;
    __syncthreads();
    if (warp == 0) {
        int w = ws[lane];
#pragma unroll
        for (int o = 1; o < 32; o <<= 1) {
            int t = __shfl_up_sync(0xffffffffu, w, o);
            if (lane >= o) w += t;
        }
        ws[lane] = w;
    }
    __syncthreads();
    int incl = v + (warp ? ws[warp - 1] : 0);
    if (idx < N_NODES) g_off[idx] = incl - val;  // exclusive, pre-block-offset
    if (tid == 1023) g_bsum[blockIdx.x] = incl;  // block total
}
__global__ void csr_scan2(int nblk)
{
    if (threadIdx.x == 0 && blockIdx.x == 0) {
        int run = 0;
        for (int b = 0; b < nblk; b++) { int t = g_bsum[b]; g_bsum[b] = run; run += t; }
    }
}
__global__ void csr_scan3()
{
    int idx = blockIdx.x * blockDim.x + threadIdx.x;
    if (idx < N_NODES) {
        int o = g_off[idx] + g_bsum[idx >> 10];
        g_off[idx] = o;
        g_cur[idx] = o;
    }
    if (idx == 0) g_off[N_NODES] = ETOT;
}
__global__ void csr_scatter(const int* __restrict__ ei)
{
    int id = blockIdx.x * blockDim.x + threadIdx.x;
    if (id < N_NODES) {                       // self loop
        int pos = atomicAdd(&g_cur[id], 1);
        g_csr[pos] = id;
    } else if (id < N_NODES + N_EDGES) {
        int e = id - N_NODES;
        int src = ei[e], dst = ei[N_EDGES + e];
        int pos = atomicAdd(&g_cur[dst], 1);
        g_csr[pos] = src;
    }
}

// ================= fused GAT: gather + online softmax + aggregate + LN1 =====
// one warp per destination node
__global__ __launch_bounds__(256)
void gat_fused(const float* __restrict__ x, const float* __restrict__ att,
               const float* __restrict__ bias, const float* __restrict__ g1,
               const float* __restrict__ be1)
{
    int node = (blockIdx.x * blockDim.x + threadIdx.x) >> 5;
    int lane = threadIdx.x & 31;
    if (node >= N_NODES) return;

    const float4* xrp = (const float4*)(g_xr + (size_t)node * HD);
    const float4* at4 = (const float4*)att;
    float4 xr4[HEADS], at[HEADS];
#pragma unroll
    for (int h = 0; h < HEADS; h++) {
        xr4[h] = xrp[h * 32 + lane];
        at[h]  = at4[h * 32 + lane];
    }

    float m[HEADS], s[HEADS];
    float4 acc[HEADS];
#pragma unroll
    for (int h = 0; h < HEADS; h++) {
        m[h] = -INFINITY; s[h] = 0.0f;
        acc[h] = make_float4(0.f, 0.f, 0.f, 0.f);
    }

    int beg = g_off[node], end = g_off[node + 1];
    for (int j = beg; j < end; j++) {
        int src = __ldg(&g_csr[j]);
        const float4* xlp = (const float4*)(g_xl + (size_t)src * HD);
        float4 v[HEADS];
        float  e[HEADS];
#pragma unroll
        for (int h = 0; h < HEADS; h++) {
            v[h] = __ldg(&xlp[h * 32 + lane]);
            float4 t = at[h], r = xr4[h], a = v[h];
            e[h] = lrelu(a.x + r.x) * t.x + lrelu(a.y + r.y) * t.y
                 + lrelu(a.z + r.z) * t.z + lrelu(a.w + r.w) * t.w;
        }
#pragma unroll
        for (int o = 16; o; o >>= 1) {
#pragma unroll
            for (int h = 0; h < HEADS; h++)
                e[h] += __shfl_xor_sync(0xffffffffu, e[h], o);
        }
#pragma unroll
        for (int h = 0; h < HEADS; h++) {
            float mn = fmaxf(m[h], e[h]);
            float sc = expf(m[h] - mn);
            float p  = expf(e[h] - mn);
            s[h] = s[h] * sc + p;
            acc[h].x = acc[h].x * sc + p * v[h].x;
            acc[h].y = acc[h].y * sc + p * v[h].y;
            acc[h].z = acc[h].z * sc + p * v[h].z;
            acc[h].w = acc[h].w * sc + p * v[h].w;
            m[h] = mn;
        }
    }

    // head mean + bias + residual + LN1
    float4 o4 = make_float4(0.f, 0.f, 0.f, 0.f);
#pragma unroll
    for (int h = 0; h < HEADS; h++) {
        float inv = 0.25f / (s[h] + 1e-16f);
        o4.x += acc[h].x * inv; o4.y += acc[h].y * inv;
        o4.z += acc[h].z * inv; o4.w += acc[h].w * inv;
    }
    float4 xb = ((const float4*)x)[(size_t)node * 32 + lane];
    float4 b4 = ((const float4*)bias)[lane];
    float4 v;
    v.x = xb.x + o4.x + b4.x;  v.y = xb.y + o4.y + b4.y;
    v.z = xb.z + o4.z + b4.z;  v.w = xb.w + o4.w + b4.w;

    float mu = wsum(v.x + v.y + v.z + v.w) * (1.0f / DIM);
    float dx = v.x - mu, dy = v.y - mu, dz = v.z - mu, dw = v.w - mu;
    float var = wsum(dx * dx + dy * dy + dz * dz + dw * dw) * (1.0f / DIM);
    float rstd = rsqrtf(var + LN_EPS);
    float4 g = ((const float4*)g1)[lane];
    float4 b = ((const float4*)be1)[lane];
    float4 o;
    o.x = dx * rstd * g.x + b.x;  o.y = dy * rstd * g.y + b.y;
    o.z = dz * rstd * g.z + b.z;  o.w = dw * rstd * g.w + b.w;
    ((float4*)g_y1)[(size_t)node * 32 + lane] = o;
}

// ---------------- LN2 on z -> out -------------------------------------------
__global__ void ln2_kernel(const float* __restrict__ g2, const float* __restrict__ be2,
                           float* __restrict__ out)
{
    int row  = (blockIdx.x * blockDim.x + threadIdx.x) >> 5;
    int lane = threadIdx.x & 31;
    if (row >= N_NODES) return;
    float4 v = ((const float4*)g_z)[(size_t)row * 32 + lane];
    float mu = wsum(v.x + v.y + v.z + v.w) * (1.0f / DIM);
    float dx = v.x - mu, dy = v.y - mu, dz = v.z - mu, dw = v.w - mu;
    float var = wsum(dx * dx + dy * dy + dz * dz + dw * dw) * (1.0f / DIM);
    float rstd = rsqrtf(var + LN_EPS);
    float4 g = ((const float4*)g2)[lane];
    float4 b = ((const float4*)be2)[lane];
    float4 o;
    o.x = dx * rstd * g.x + b.x;  o.y = dy * rstd * g.y + b.y;
    o.z = dz * rstd * g.z + b.z;  o.w = dw * rstd * g.w + b.w;
    ((float4*)out)[(size_t)row * 32 + lane] = o;
}

// ---------------- launch -----------------------------------------------------
extern "C" void kernel_launch(void* const* d_in, const int* in_sizes, int n_in,
                              void* d_out, int out_size)
{
    const float* x    = (const float*)d_in[0];
    const int*   ei   = (const int*)d_in[1];
    const float* Wl   = (const float*)d_in[2];
    const float* bl   = (const float*)d_in[3];
    const float* Wr   = (const float*)d_in[4];
    const float* br   = (const float*)d_in[5];
    const float* att  = (const float*)d_in[6];
    const float* bias = (const float*)d_in[7];
    const float* g1   = (const float*)d_in[8];
    const float* be1  = (const float*)d_in[9];
    const float* W1   = (const float*)d_in[10];
    const float* b1   = (const float*)d_in[11];
    const float* W2   = (const float*)d_in[12];
    const float* b2   = (const float*)d_in[13];
    const float* g2   = (const float*)d_in[14];
    const float* be2  = (const float*)d_in[15];
    float* out = (float*)d_out;

    float *p_xl, *p_xr, *p_y1, *p_mid, *p_z;
    cudaGetSymbolAddress((void**)&p_xl,  g_xl);
    cudaGetSymbolAddress((void**)&p_xr,  g_xr);
    cudaGetSymbolAddress((void**)&p_y1,  g_y1);
    cudaGetSymbolAddress((void**)&p_mid, g_mid);
    cudaGetSymbolAddress((void**)&p_z,   g_z);

    const int MB = (N_NODES + 127) / 128;           // 391
    const int SNBLK = (N_NODES + 1023) / 1024;      // 49

    // CSR build (independent of GEMMs; stream-serialized anyway)
    csr_init<<<(N_NODES + 255) / 256, 256>>>();
    csr_hist<<<(N_EDGES + 255) / 256, 256>>>(ei);
    csr_scan1<<<SNBLK, 1024>>>();
    csr_scan2<<<1, 32>>>(SNBLK);
    csr_scan3<<<(N_NODES + 255) / 256, 256>>>();
    csr_scatter<<<(N_NODES + N_EDGES + 255) / 256, 256>>>(ei);

    gemm_mma<0><<<dim3(MB, HD / 128), 256>>>(x, Wl, bl, nullptr, p_xl, N_NODES, HD, DIM);
    gemm_mma<0><<<dim3(MB, HD / 128), 256>>>(x, Wr, br, nullptr, p_xr, N_NODES, HD, DIM);

    gat_fused<<<(N_NODES * 32 + 255) / 256, 256>>>(x, att, bias, g1, be1);

    gemm_mma<1><<<dim3(MB, (2 * DIM) / 128), 256>>>(p_y1, W1, b1, nullptr, p_mid,
                                                    N_NODES, 2 * DIM, DIM);
    gemm_mma<2><<<dim3(MB, DIM / 128), 256>>>(p_mid, W2, b2, p_y1, p_z,
                                              N_NODES, DIM, 2 * DIM);
    ln2_kernel<<<(N_NODES * 32) / 256, 256>>>(g2, be2, out);
}